// round 7
// baseline (speedup 1.0000x reference)
#include <cuda_runtime.h>
#include <cuda_fp16.h>
#include <cstdint>
#include <math.h>

// ---------------- problem constants (fixed by setup_inputs) ----------------
#define NT    21
#define S_SP  1560
#define NTS   32760
#define DIM   1536
#define ENC   768
#define NA    32
#define NHEAD 12
#define HD    128
#define KVN   3072

// ---------------- scratch (static device globals) ----------------
__device__ float  g_mm[4];
__device__ float  g_ct[NTS * 64];
__device__ float  g_st[NTS * 64];
__device__ float  g_kv[(size_t)NT * NA * KVN];   // kv after GEMM (fp32)
__device__ __half g_xh[(size_t)NTS * DIM];       // x in fp16
__device__ __half g_qwh[(size_t)DIM * DIM];      // q_w in fp16
__device__ __half g_pwh[(size_t)DIM * DIM];      // proj_w in fp16
__device__ __half g_qh[(size_t)NTS * DIM];       // q after GEMM+RoPE (fp16)
__device__ __half g_attnh[(size_t)NTS * DIM];    // attention output (fp16)

// ---------------- fp32 -> fp16 conversion ----------------
__global__ void f2h_kernel(const float* __restrict__ in, __half* __restrict__ out, long n4) {
    long i = (long)blockIdx.x * blockDim.x + threadIdx.x;
    if (i >= n4) return;
    float4 v = reinterpret_cast<const float4*>(in)[i];
    __half2 h0 = __floats2half2_rn(v.x, v.y);
    __half2 h1 = __floats2half2_rn(v.z, v.w);
    uint2 o;
    o.x = *reinterpret_cast<uint32_t*>(&h0);
    o.y = *reinterpret_cast<uint32_t*>(&h1);
    reinterpret_cast<uint2*>(out)[i] = o;
}

// ---------------- min/max of the two attn-map rows ----------------
__global__ void minmax_kernel(const float* __restrict__ m, int n) {
    const int tid = threadIdx.x, lane = tid & 31, warp = tid >> 5;
    float mn0 = 1e30f, mx0 = -1e30f, mn1 = 1e30f, mx1 = -1e30f;
    for (int i = tid; i < n; i += blockDim.x) {
        float a = m[i], b = m[n + i];
        mn0 = fminf(mn0, a); mx0 = fmaxf(mx0, a);
        mn1 = fminf(mn1, b); mx1 = fmaxf(mx1, b);
    }
    #pragma unroll
    for (int o = 16; o > 0; o >>= 1) {
        mn0 = fminf(mn0, __shfl_xor_sync(0xffffffffu, mn0, o));
        mx0 = fmaxf(mx0, __shfl_xor_sync(0xffffffffu, mx0, o));
        mn1 = fminf(mn1, __shfl_xor_sync(0xffffffffu, mn1, o));
        mx1 = fmaxf(mx1, __shfl_xor_sync(0xffffffffu, mx1, o));
    }
    __shared__ float s0[32], s1[32], s2[32], s3[32];
    if (lane == 0) { s0[warp] = mn0; s1[warp] = mx0; s2[warp] = mn1; s3[warp] = mx1; }
    __syncthreads();
    if (warp == 0) {
        int nw = blockDim.x >> 5;
        mn0 = (lane < nw) ? s0[lane] : 1e30f;
        mx0 = (lane < nw) ? s1[lane] : -1e30f;
        mn1 = (lane < nw) ? s2[lane] : 1e30f;
        mx1 = (lane < nw) ? s3[lane] : -1e30f;
        #pragma unroll
        for (int o = 16; o > 0; o >>= 1) {
            mn0 = fminf(mn0, __shfl_xor_sync(0xffffffffu, mn0, o));
            mx0 = fmaxf(mx0, __shfl_xor_sync(0xffffffffu, mx0, o));
            mn1 = fminf(mn1, __shfl_xor_sync(0xffffffffu, mn1, o));
            mx1 = fmaxf(mx1, __shfl_xor_sync(0xffffffffu, mx1, o));
        }
        if (lane == 0) { g_mm[0] = mn0; g_mm[1] = mx0; g_mm[2] = mn1; g_mm[3] = mx1; }
    }
}

// ---------------- per-(token,freq) cos/sin table ----------------
__global__ void table_kernel(const float* __restrict__ m, int n) {
    int idx = blockIdx.x * blockDim.x + threadIdx.x;
    if (idx >= n * 64) return;
    int t = idx >> 6, i = idx & 63;
    float mn0 = g_mm[0], mx0 = g_mm[1], mn1 = g_mm[2], mx1 = g_mm[3];
    float m0 = m[t], m1 = m[n + t];
    float h1 = (m0 - mn0) / (mx0 - mn0 + 1e-8f) * 4.0f;
    float h2 = (m1 - mn1) / (mx1 - mn1 + 1e-8f) * 4.0f + 20.0f;
    float pos = (m0 >= m1) ? h1 : h2;
    float freq = expf(-(float)i * (2.0f / 128.0f) * 9.210340371976184f);
    float s, c;
    sincosf(pos * freq, &s, &c);
    g_ct[idx] = c;
    g_st[idx] = s;
}

// ---------------- fp16 GEMM: C[M,1536] = A[M,1536] @ B[1536,1536]^T + bias --
// Block tile 128x256, 8 warps (2x4), warp tile 64x64. BK=32, 5-stage cp.async.
// Smem rows padded to 80B (40 halves): r*80 mod 128 permutes the 8 16B-slots
// (5 odd) -> conflict-free ldmatrix without XOR swizzle.
#define GBK 32
#define GROWB 80                              // bytes per padded smem row
#define A_ST_BYTES (128 * GROWB)              // 10240
#define B_ST_BYTES (256 * GROWB)              // 20480
#define G_STAGE (A_ST_BYTES + B_ST_BYTES)     // 30720
#define G_STAGES 5
#define SMEM_G (G_STAGES * G_STAGE)           // 153600
#define GKT (1536 / GBK)                      // 48

__device__ __forceinline__ void mma16816(float* d, const uint32_t* a, const uint32_t* b) {
    asm volatile(
        "mma.sync.aligned.m16n8k16.row.col.f32.f16.f16.f32 "
        "{%0,%1,%2,%3}, {%4,%5,%6,%7}, {%8,%9}, {%0,%1,%2,%3};\n"
        : "+f"(d[0]), "+f"(d[1]), "+f"(d[2]), "+f"(d[3])
        : "r"(a[0]), "r"(a[1]), "r"(a[2]), "r"(a[3]), "r"(b[0]), "r"(b[1]));
}
__device__ __forceinline__ void ldsm4(uint32_t* r, uint32_t addr) {
    asm volatile("ldmatrix.sync.aligned.m8n8.x4.shared.b16 {%0,%1,%2,%3}, [%4];"
                 : "=r"(r[0]), "=r"(r[1]), "=r"(r[2]), "=r"(r[3]) : "r"(addr));
}

template <int EPI, typename OT>   // EPI 0: bias, fp32 out. EPI 1: bias+RoPE, fp16 out.
__global__ __launch_bounds__(256)
void gemm_h(const __half* __restrict__ A, const __half* __restrict__ B,
            const float* __restrict__ bias, OT* __restrict__ C, int M) {
    extern __shared__ char sm[];
    const int tid = threadIdx.x, lane = tid & 31, warp = tid >> 5;
    const int wm = warp >> 2, wn = warp & 3;       // 2 x 4 warps, warp tile 64x64
    const int row0 = blockIdx.y * 128, col0 = blockIdx.x * 256;

    float acc[4][8][4];
    #pragma unroll
    for (int i = 0; i < 4; i++)
        #pragma unroll
        for (int j = 0; j < 8; j++)
            #pragma unroll
            for (int r = 0; r < 4; r++) acc[i][j][r] = 0.f;

    // stage loader: A 512 chunks (2/thread) + B 1024 chunks (4/thread) of 16B
    auto load_stage = [&](int kt, int s) {
        const int k0 = kt * GBK;
        char* base = sm + s * G_STAGE;
        #pragma unroll
        for (int j = 0; j < 2; j++) {
            int id = tid + j * 256;
            int r = id >> 2, c = id & 3;
            uint32_t sa = (uint32_t)__cvta_generic_to_shared(base + r * GROWB + c * 16);
            const __half* ga = A + (size_t)(row0 + r) * 1536 + k0 + c * 8;
            int sz = (row0 + r < M) ? 16 : 0;
            asm volatile("cp.async.cg.shared.global [%0], [%1], 16, %2;\n"
                         :: "r"(sa), "l"(ga), "r"(sz) : "memory");
        }
        char* bb = base + A_ST_BYTES;
        #pragma unroll
        for (int j = 0; j < 4; j++) {
            int id = tid + j * 256;
            int r = id >> 2, c = id & 3;
            uint32_t sb = (uint32_t)__cvta_generic_to_shared(bb + r * GROWB + c * 16);
            const __half* gb = B + (size_t)(col0 + r) * 1536 + k0 + c * 8;
            asm volatile("cp.async.cg.shared.global [%0], [%1], 16;\n"
                         :: "r"(sb), "l"(gb) : "memory");
        }
        asm volatile("cp.async.commit_group;\n" ::: "memory");
    };

    load_stage(0, 0);
    load_stage(1, 1);
    load_stage(2, 2);
    load_stage(3, 3);

    const int lrow = lane & 15;
    const int lkh  = lane >> 4;

    for (int kt = 0; kt < GKT; kt++) {
        const int rem = GKT - 1 - kt;
        if (rem >= 3)      { asm volatile("cp.async.wait_group 3;\n" ::: "memory"); }
        else if (rem == 2) { asm volatile("cp.async.wait_group 2;\n" ::: "memory"); }
        else if (rem == 1) { asm volatile("cp.async.wait_group 1;\n" ::: "memory"); }
        else               { asm volatile("cp.async.wait_group 0;\n" ::: "memory"); }
        __syncthreads();
        if (kt + 4 < GKT) load_stage(kt + 4, (kt + 4) % G_STAGES);

        const char* Ab = sm + (kt % G_STAGES) * G_STAGE;
        const char* Bb = Ab + A_ST_BYTES;

        #pragma unroll
        for (int kk = 0; kk < 2; kk++) {
            const int cidx = kk * 2 + lkh;            // 16B chunk within row
            uint32_t af[4][4], bf[8][2];
            #pragma unroll
            for (int im = 0; im < 4; im++) {
                int r = wm * 64 + im * 16 + lrow;
                uint32_t addr = (uint32_t)__cvta_generic_to_shared(
                    Ab + r * GROWB + cidx * 16);
                ldsm4(af[im], addr);
            }
            #pragma unroll
            for (int i2 = 0; i2 < 4; i2++) {
                int r = wn * 64 + i2 * 16 + lrow;
                uint32_t addr = (uint32_t)__cvta_generic_to_shared(
                    Bb + r * GROWB + cidx * 16);
                uint32_t t[4];
                ldsm4(t, addr);
                bf[i2 * 2][0] = t[0];     bf[i2 * 2][1] = t[2];
                bf[i2 * 2 + 1][0] = t[1]; bf[i2 * 2 + 1][1] = t[3];
            }
            #pragma unroll
            for (int im = 0; im < 4; im++)
                #pragma unroll
                for (int in = 0; in < 8; in++)
                    mma16816(acc[im][in], af[im], bf[in]);
        }
    }

    // ---- epilogue ----
    const int tr = lane >> 2, tc = lane & 3;
    #pragma unroll
    for (int im = 0; im < 4; im++)
        #pragma unroll
        for (int in = 0; in < 8; in++)
            #pragma unroll
            for (int h = 0; h < 2; h++) {
                int row = row0 + wm * 64 + im * 16 + tr + h * 8;
                if (row >= M) continue;
                int col = col0 + wn * 64 + in * 8 + (tc << 1);
                float v0 = acc[im][in][h * 2 + 0] + bias[col];
                float v1 = acc[im][in][h * 2 + 1] + bias[col + 1];
                if (EPI == 1) {
                    int fi = (col & 127) >> 1;
                    float cc = g_ct[row * 64 + fi], ss = g_st[row * 64 + fi];
                    float a = v0, b = v1;
                    v0 = a * cc - b * ss;
                    v1 = b * cc + a * ss;
                    __half2 hh = __floats2half2_rn(v0, v1);
                    *reinterpret_cast<__half2*>((__half*)C + (size_t)row * DIM + col) = hh;
                } else {
                    *reinterpret_cast<float2*>((float*)C + (size_t)row * DIM + col) =
                        make_float2(v0, v1);
                }
            }
}

// ---------------- SIMT TF32 GEMM for the small kv projection ----------------
__device__ __forceinline__ uint32_t f2tf32(float f) {
    uint32_t r;
    asm("cvt.rna.tf32.f32 %0, %1;" : "=r"(r) : "f"(f));
    return r;
}
__device__ __forceinline__ void mma_tf32(float* d, const uint32_t* a, const uint32_t* b) {
    asm volatile(
        "mma.sync.aligned.m16n8k8.row.col.f32.tf32.tf32.f32 "
        "{%0,%1,%2,%3}, {%4,%5,%6,%7}, {%8,%9}, {%0,%1,%2,%3};\n"
        : "+f"(d[0]), "+f"(d[1]), "+f"(d[2]), "+f"(d[3])
        : "r"(a[0]), "r"(a[1]), "r"(a[2]), "r"(a[3]), "r"(b[0]), "r"(b[1]));
}
#define SMEM_KV (2 * 2 * 128 * 32 * 4)

__global__ __launch_bounds__(256)
void gemm_kv(const float* __restrict__ A, const float* __restrict__ B,
             const float* __restrict__ bias, float* __restrict__ C,
             int M, int N, int K) {
    extern __shared__ float smf[];
    float* As = smf;
    float* Bs = smf + 2 * 4096;
    const int tid = threadIdx.x, lane = tid & 31, warp = tid >> 5;
    const int wm = warp >> 2, wn = warp & 3;
    const int tr = lane >> 2, tc = lane & 3;
    const int row0 = blockIdx.y * 128, col0 = blockIdx.x * 128;
    const int KT = K >> 5;

    float acc[4][4][4];
    #pragma unroll
    for (int i = 0; i < 4; i++)
        #pragma unroll
        for (int j = 0; j < 4; j++)
            #pragma unroll
            for (int r = 0; r < 4; r++) acc[i][j][r] = 0.f;

    auto tile_load = [&](int kt, int buf) {
        int k0 = kt << 5;
        #pragma unroll
        for (int j = 0; j < 4; j++) {
            int L = tid + j * 256;
            int r = L >> 3, c4 = L & 7;
            int soff = buf * 4096 + r * 32 + ((c4 ^ (r & 7)) << 2);
            const float* ga = A + (size_t)(row0 + r) * K + k0 + (c4 << 2);
            uint32_t sa = (uint32_t)__cvta_generic_to_shared(As + soff);
            int sz = (row0 + r < M) ? 16 : 0;
            asm volatile("cp.async.cg.shared.global [%0], [%1], 16, %2;\n"
                         :: "r"(sa), "l"(ga), "r"(sz) : "memory");
            const float* gb = B + (size_t)(col0 + r) * K + k0 + (c4 << 2);
            uint32_t sb = (uint32_t)__cvta_generic_to_shared(Bs + soff);
            asm volatile("cp.async.cg.shared.global [%0], [%1], 16;\n"
                         :: "r"(sb), "l"(gb) : "memory");
        }
        asm volatile("cp.async.commit_group;\n" ::: "memory");
    };

    tile_load(0, 0);
    for (int kt = 0; kt < KT; ++kt) {
        asm volatile("cp.async.wait_group 0;\n" ::: "memory");
        __syncthreads();
        const int cur = kt & 1;
        if (kt + 1 < KT) tile_load(kt + 1, cur ^ 1);
        const float* Ab = As + cur * 4096;
        const float* Bb = Bs + cur * 4096;
        #pragma unroll
        for (int kk = 0; kk < 4; kk++) {
            const int kb = kk << 3;
            uint32_t af[4][4], bf[4][2];
            #pragma unroll
            for (int im = 0; im < 4; im++) {
                int rb = wm * 64 + im * 16;
                int r1 = rb + tr, r2 = rb + tr + 8;
                int k1 = kb + tc, k2 = kb + tc + 4;
                af[im][0] = f2tf32(Ab[r1 * 32 + (((k1 >> 2) ^ (r1 & 7)) << 2) + (k1 & 3)]);
                af[im][1] = f2tf32(Ab[r2 * 32 + (((k1 >> 2) ^ (r2 & 7)) << 2) + (k1 & 3)]);
                af[im][2] = f2tf32(Ab[r1 * 32 + (((k2 >> 2) ^ (r1 & 7)) << 2) + (k2 & 3)]);
                af[im][3] = f2tf32(Ab[r2 * 32 + (((k2 >> 2) ^ (r2 & 7)) << 2) + (k2 & 3)]);
            }
            #pragma unroll
            for (int in = 0; in < 4; in++) {
                int nb = wn * 32 + in * 8 + tr;
                int k1 = kb + tc, k2 = kb + tc + 4;
                bf[in][0] = f2tf32(Bb[nb * 32 + (((k1 >> 2) ^ (nb & 7)) << 2) + (k1 & 3)]);
                bf[in][1] = f2tf32(Bb[nb * 32 + (((k2 >> 2) ^ (nb & 7)) << 2) + (k2 & 3)]);
            }
            #pragma unroll
            for (int im = 0; im < 4; im++)
                #pragma unroll
                for (int in = 0; in < 4; in++)
                    mma_tf32(acc[im][in], af[im], bf[in]);
        }
        __syncthreads();
    }

    #pragma unroll
    for (int im = 0; im < 4; im++)
        #pragma unroll
        for (int in = 0; in < 4; in++)
            #pragma unroll
            for (int h = 0; h < 2; h++) {
                int row = row0 + wm * 64 + im * 16 + tr + h * 8;
                if (row >= M) continue;
                int col = col0 + wn * 32 + in * 8 + (tc << 1);
                float v0 = acc[im][in][h * 2 + 0] + bias[col];
                float v1 = acc[im][in][h * 2 + 1] + bias[col + 1];
                if (col < DIM) {   // k half: bucket-centre RoPE
                    int a = row & 31;
                    float pos = (a < 16) ? 2.0f : 22.0f;
                    int fi = (col & 127) >> 1;
                    float freq = expf(-(float)fi * (2.0f / 128.0f) * 9.210340371976184f);
                    float s, c;
                    sincosf(pos * freq, &s, &c);
                    float o0 = v0 * c - v1 * s;
                    float o1 = v1 * c + v0 * s;
                    v0 = o0; v1 = o1;
                }
                *reinterpret_cast<float2*>(C + (size_t)row * N + col) = make_float2(v0, v1);
            }
}

// ---------------- attention: per (frame, head), KV len 32 -------------------
// q fp16 in, fp16 out. K padded rows for conflict-free float4 lane reads,
// probs staged in smem (no shfl in AV loop).
#define SMEM_ATTN ((32 * 132 + 32 * 128 + 8 * 4 * 128 + 8 * 4 * 32) * 4)

__global__ __launch_bounds__(256)
void attn_kernel(const __half* __restrict__ q, const float* __restrict__ kv,
                 __half* __restrict__ out) {
    extern __shared__ float smA[];
    float* ks = smA;                 // [32][132] padded
    float* vs = ks + 32 * 132;       // [32][128]
    float* qb = vs + 32 * 128;       // [8 warps][4 rows][128]
    float* ps = qb + 8 * 4 * 128;    // [8 warps][4 rows][32]

    const int fh = blockIdx.x;
    const int f = fh / NHEAD, h = fh % NHEAD;
    const int tid = threadIdx.x, lane = tid & 31, warp = tid >> 5;

    const float* kvb = kv + (size_t)f * NA * KVN + h * HD;
    for (int idx = tid; idx < NA * HD; idx += 256) {
        int a = idx >> 7, d = idx & 127;
        ks[a * 132 + d] = kvb[(size_t)a * KVN + d];
        vs[idx] = kvb[(size_t)a * KVN + DIM + d];
    }
    __syncthreads();

    float* qw = qb + warp * 4 * 128;
    float* pw = ps + warp * 4 * 32;

    const int sbase = blockIdx.y * 128 + warp * 16;
    for (int g = 0; g < 4; ++g) {
        int s0 = sbase + g * 4;
        // load 4 q rows (fp16 -> fp32 smem)
        #pragma unroll
        for (int r = 0; r < 4; r++) {
            int s = min(s0 + r, S_SP - 1);
            uint2 raw = *reinterpret_cast<const uint2*>(
                q + (size_t)(f * S_SP + s) * DIM + h * HD + lane * 4);
            __half2 h0 = *reinterpret_cast<__half2*>(&raw.x);
            __half2 h1 = *reinterpret_cast<__half2*>(&raw.y);
            float2 f0 = __half22float2(h0);
            float2 f1 = __half22float2(h1);
            *reinterpret_cast<float4*>(qw + r * 128 + lane * 4) =
                make_float4(f0.x, f0.y, f1.x, f1.y);
        }
        __syncwarp();

        // scores: lane = kv index a; float4 over d
        float sc[4] = {0.f, 0.f, 0.f, 0.f};
        #pragma unroll 8
        for (int d4 = 0; d4 < 32; d4++) {
            float4 k4 = *reinterpret_cast<const float4*>(ks + lane * 132 + d4 * 4);
            #pragma unroll
            for (int r = 0; r < 4; r++) {
                float4 q4 = *reinterpret_cast<const float4*>(qw + r * 128 + d4 * 4);
                sc[r] = fmaf(q4.x, k4.x, sc[r]);
                sc[r] = fmaf(q4.y, k4.y, sc[r]);
                sc[r] = fmaf(q4.z, k4.z, sc[r]);
                sc[r] = fmaf(q4.w, k4.w, sc[r]);
            }
        }

        // softmax over 32 kv (lane-wide)
        #pragma unroll
        for (int r = 0; r < 4; r++) {
            float x = sc[r] * 0.08838834764831845f;
            float mx = x;
            #pragma unroll
            for (int o = 16; o > 0; o >>= 1) mx = fmaxf(mx, __shfl_xor_sync(0xffffffffu, mx, o));
            float e = expf(x - mx);
            float sum = e;
            #pragma unroll
            for (int o = 16; o > 0; o >>= 1) sum += __shfl_xor_sync(0xffffffffu, sum, o);
            pw[r * 32 + lane] = e / sum;
        }
        __syncwarp();

        // AV: lane owns d-chunk lane*4..+3
        float4 ac[4];
        #pragma unroll
        for (int r = 0; r < 4; r++) ac[r] = make_float4(0.f, 0.f, 0.f, 0.f);
        #pragma unroll
        for (int a4 = 0; a4 < 8; a4++) {
            float4 pv[4];
            #pragma unroll
            for (int r = 0; r < 4; r++)
                pv[r] = *reinterpret_cast<const float4*>(pw + r * 32 + a4 * 4);
            #pragma unroll
            for (int j = 0; j < 4; j++) {
                float4 va = *reinterpret_cast<const float4*>(vs + (a4 * 4 + j) * 128 + lane * 4);
                #pragma unroll
                for (int r = 0; r < 4; r++) {
                    float pa = (j == 0) ? pv[r].x : (j == 1) ? pv[r].y : (j == 2) ? pv[r].z : pv[r].w;
                    ac[r].x = fmaf(pa, va.x, ac[r].x);
                    ac[r].y = fmaf(pa, va.y, ac[r].y);
                    ac[r].z = fmaf(pa, va.z, ac[r].z);
                    ac[r].w = fmaf(pa, va.w, ac[r].w);
                }
            }
        }
        #pragma unroll
        for (int r = 0; r < 4; r++) {
            int s = s0 + r;
            if (s < S_SP) {
                __half2 h0 = __floats2half2_rn(ac[r].x, ac[r].y);
                __half2 h1 = __floats2half2_rn(ac[r].z, ac[r].w);
                uint2 o;
                o.x = *reinterpret_cast<uint32_t*>(&h0);
                o.y = *reinterpret_cast<uint32_t*>(&h1);
                *reinterpret_cast<uint2*>(
                    out + (size_t)(f * S_SP + s) * DIM + h * HD + lane * 4) = o;
            }
        }
        __syncwarp();
    }
}

// ---------------- launch ----------------
extern "C" void kernel_launch(void* const* d_in, const int* in_sizes, int n_in,
                              void* d_out, int out_size) {
    const float* x      = (const float*)d_in[0];
    const float* enc    = (const float*)d_in[1];
    const float* m      = (const float*)d_in[2];
    const float* q_w    = (const float*)d_in[3];
    const float* q_b    = (const float*)d_in[4];
    const float* kv_w   = (const float*)d_in[5];
    const float* kv_b   = (const float*)d_in[6];
    const float* proj_w = (const float*)d_in[7];
    const float* proj_b = (const float*)d_in[8];
    float* out = (float*)d_out;

    float* kvbuf;
    __half *xh, *qwh, *pwh, *qh, *attnh;
    cudaGetSymbolAddress((void**)&kvbuf, g_kv);
    cudaGetSymbolAddress((void**)&xh, g_xh);
    cudaGetSymbolAddress((void**)&qwh, g_qwh);
    cudaGetSymbolAddress((void**)&pwh, g_pwh);
    cudaGetSymbolAddress((void**)&qh, g_qh);
    cudaGetSymbolAddress((void**)&attnh, g_attnh);

    cudaFuncSetAttribute(gemm_h<0, float>, cudaFuncAttributeMaxDynamicSharedMemorySize, SMEM_G);
    cudaFuncSetAttribute(gemm_h<1, __half>, cudaFuncAttributeMaxDynamicSharedMemorySize, SMEM_G);
    cudaFuncSetAttribute(gemm_kv, cudaFuncAttributeMaxDynamicSharedMemorySize, SMEM_KV);
    cudaFuncSetAttribute(attn_kernel, cudaFuncAttributeMaxDynamicSharedMemorySize, SMEM_ATTN);

    minmax_kernel<<<1, 1024>>>(m, NTS);
    table_kernel<<<(NTS * 64 + 255) / 256, 256>>>(m, NTS);

    long nx4 = (long)NTS * DIM / 4, nw4 = (long)DIM * DIM / 4;
    f2h_kernel<<<(unsigned)((nx4 + 255) / 256), 256>>>(x, xh, nx4);
    f2h_kernel<<<(unsigned)((nw4 + 255) / 256), 256>>>(q_w, qwh, nw4);
    f2h_kernel<<<(unsigned)((nw4 + 255) / 256), 256>>>(proj_w, pwh, nw4);

    // q = x @ q_w^T + q_b, fused token RoPE, fp16 out
    gemm_h<1, __half><<<dim3(DIM / 256, (NTS + 127) / 128), 256, SMEM_G>>>(
        xh, qwh, q_b, qh, NTS);
    // kv = enc @ kv_w^T + kv_b, bucket RoPE on k half
    gemm_kv<<<dim3(KVN / 128, (NT * NA + 127) / 128), 256, SMEM_KV>>>(
        enc, kv_w, kv_b, kvbuf, NT * NA, KVN, ENC);
    // cross attention (fp16 in, fp16 out)
    attn_kernel<<<dim3(NT * NHEAD, 13), 256, SMEM_ATTN>>>(qh, kvbuf, attnh);
    // out = attn @ proj_w^T + proj_b, fp32 out
    gemm_h<0, float><<<dim3(DIM / 256, (NTS + 127) / 128), 256, SMEM_G>>>(
        attnh, pwh, proj_b, out, NTS);
}

// round 8
// speedup vs baseline: 1.3922x; 1.3922x over previous
#include <cuda_runtime.h>
#include <cuda_fp16.h>
#include <cstdint>
#include <math.h>

// ---------------- problem constants (fixed by setup_inputs) ----------------
#define NT    21
#define S_SP  1560
#define NTS   32760
#define DIM   1536
#define ENC   768
#define NA    32
#define NHEAD 12
#define HD    128
#define KVN   3072

// ---------------- scratch (static device globals) ----------------
__device__ float  g_mm[4];
__device__ float  g_ct[NTS * 64];
__device__ float  g_st[NTS * 64];
__device__ float  g_kv[(size_t)NT * NA * KVN];   // kv after GEMM (fp32)
__device__ __half g_xh[(size_t)NTS * DIM];       // x in fp16
__device__ __half g_qwh[(size_t)DIM * DIM];      // q_w in fp16
__device__ __half g_pwh[(size_t)DIM * DIM];      // proj_w in fp16
__device__ __half g_qh[(size_t)NTS * DIM];       // q after GEMM+RoPE (fp16)
__device__ __half g_attnh[(size_t)NTS * DIM];    // attention output (fp16)

// ---------------- fp32 -> fp16 conversion ----------------
__global__ void f2h_kernel(const float* __restrict__ in, __half* __restrict__ out, long n4) {
    long i = (long)blockIdx.x * blockDim.x + threadIdx.x;
    if (i >= n4) return;
    float4 v = reinterpret_cast<const float4*>(in)[i];
    __half2 h0 = __floats2half2_rn(v.x, v.y);
    __half2 h1 = __floats2half2_rn(v.z, v.w);
    uint2 o;
    o.x = *reinterpret_cast<uint32_t*>(&h0);
    o.y = *reinterpret_cast<uint32_t*>(&h1);
    reinterpret_cast<uint2*>(out)[i] = o;
}

// ---------------- min/max of the two attn-map rows ----------------
__global__ void minmax_kernel(const float* __restrict__ m, int n) {
    const int tid = threadIdx.x, lane = tid & 31, warp = tid >> 5;
    float mn0 = 1e30f, mx0 = -1e30f, mn1 = 1e30f, mx1 = -1e30f;
    for (int i = tid; i < n; i += blockDim.x) {
        float a = m[i], b = m[n + i];
        mn0 = fminf(mn0, a); mx0 = fmaxf(mx0, a);
        mn1 = fminf(mn1, b); mx1 = fmaxf(mx1, b);
    }
    #pragma unroll
    for (int o = 16; o > 0; o >>= 1) {
        mn0 = fminf(mn0, __shfl_xor_sync(0xffffffffu, mn0, o));
        mx0 = fmaxf(mx0, __shfl_xor_sync(0xffffffffu, mx0, o));
        mn1 = fminf(mn1, __shfl_xor_sync(0xffffffffu, mn1, o));
        mx1 = fmaxf(mx1, __shfl_xor_sync(0xffffffffu, mx1, o));
    }
    __shared__ float s0[32], s1[32], s2[32], s3[32];
    if (lane == 0) { s0[warp] = mn0; s1[warp] = mx0; s2[warp] = mn1; s3[warp] = mx1; }
    __syncthreads();
    if (warp == 0) {
        int nw = blockDim.x >> 5;
        mn0 = (lane < nw) ? s0[lane] : 1e30f;
        mx0 = (lane < nw) ? s1[lane] : -1e30f;
        mn1 = (lane < nw) ? s2[lane] : 1e30f;
        mx1 = (lane < nw) ? s3[lane] : -1e30f;
        #pragma unroll
        for (int o = 16; o > 0; o >>= 1) {
            mn0 = fminf(mn0, __shfl_xor_sync(0xffffffffu, mn0, o));
            mx0 = fmaxf(mx0, __shfl_xor_sync(0xffffffffu, mx0, o));
            mn1 = fminf(mn1, __shfl_xor_sync(0xffffffffu, mn1, o));
            mx1 = fmaxf(mx1, __shfl_xor_sync(0xffffffffu, mx1, o));
        }
        if (lane == 0) { g_mm[0] = mn0; g_mm[1] = mx0; g_mm[2] = mn1; g_mm[3] = mx1; }
    }
}

// ---------------- per-(token,freq) cos/sin table ----------------
__global__ void table_kernel(const float* __restrict__ m, int n) {
    int idx = blockIdx.x * blockDim.x + threadIdx.x;
    if (idx >= n * 64) return;
    int t = idx >> 6, i = idx & 63;
    float mn0 = g_mm[0], mx0 = g_mm[1], mn1 = g_mm[2], mx1 = g_mm[3];
    float m0 = m[t], m1 = m[n + t];
    float h1 = (m0 - mn0) / (mx0 - mn0 + 1e-8f) * 4.0f;
    float h2 = (m1 - mn1) / (mx1 - mn1 + 1e-8f) * 4.0f + 20.0f;
    float pos = (m0 >= m1) ? h1 : h2;
    float freq = expf(-(float)i * (2.0f / 128.0f) * 9.210340371976184f);
    float s, c;
    sincosf(pos * freq, &s, &c);
    g_ct[idx] = c;
    g_st[idx] = s;
}

// ---------------- fp16 GEMM: C[M,1536] = A[M,1536] @ B[1536,1536]^T + bias --
// (R6 proven config) ldmatrix + mma.m16n8k16, 128x128 tile, BK=64, 3 stages.
// EPI 0: bias only, fp32 out. EPI 1: bias + per-token RoPE, fp16 out.
#define HBK 64
#define HSTAGE_BYTES (128 * HBK * 2 * 2)      // A tile 16KB + B tile 16KB
#define HSTAGES 3
#define SMEM_H (HSTAGES * HSTAGE_BYTES)       // 98304 -> 2 CTAs/SM
#define HKT (1536 / HBK)                      // 24

__device__ __forceinline__ void mma16816(float* d, const uint32_t* a, const uint32_t* b) {
    asm volatile(
        "mma.sync.aligned.m16n8k16.row.col.f32.f16.f16.f32 "
        "{%0,%1,%2,%3}, {%4,%5,%6,%7}, {%8,%9}, {%0,%1,%2,%3};\n"
        : "+f"(d[0]), "+f"(d[1]), "+f"(d[2]), "+f"(d[3])
        : "r"(a[0]), "r"(a[1]), "r"(a[2]), "r"(a[3]), "r"(b[0]), "r"(b[1]));
}
__device__ __forceinline__ void ldsm4(uint32_t* r, uint32_t addr) {
    asm volatile("ldmatrix.sync.aligned.m8n8.x4.shared.b16 {%0,%1,%2,%3}, [%4];"
                 : "=r"(r[0]), "=r"(r[1]), "=r"(r[2]), "=r"(r[3]) : "r"(addr));
}

template <int EPI, typename OT>
__global__ __launch_bounds__(256)
void gemm_h(const __half* __restrict__ A, const __half* __restrict__ B,
            const float* __restrict__ bias, OT* __restrict__ C, int M) {
    extern __shared__ char sm[];
    const int tid = threadIdx.x, lane = tid & 31, warp = tid >> 5;
    const int wm = warp >> 2, wn = warp & 3;         // 2 x 4 warps, warp tile 64x32
    const int row0 = blockIdx.y * 128, col0 = blockIdx.x * 128;

    float acc[4][4][4];
    #pragma unroll
    for (int i = 0; i < 4; i++)
        #pragma unroll
        for (int j = 0; j < 4; j++)
            #pragma unroll
            for (int r = 0; r < 4; r++) acc[i][j][r] = 0.f;

    auto load_stage = [&](int kt, int s) {
        const int k0 = kt * HBK;
        char* base = sm + s * HSTAGE_BYTES;
        #pragma unroll
        for (int j = 0; j < 4; j++) {
            int id = tid + j * 256;
            int r = id >> 3, c = id & 7;
            int phys = (c ^ (r & 7)) << 4;
            uint32_t sa = (uint32_t)__cvta_generic_to_shared(base + r * 128 + phys);
            const __half* ga = A + (size_t)(row0 + r) * 1536 + k0 + c * 8;
            int sz = (row0 + r < M) ? 16 : 0;
            asm volatile("cp.async.cg.shared.global [%0], [%1], 16, %2;\n"
                         :: "r"(sa), "l"(ga), "r"(sz) : "memory");
            uint32_t sb = (uint32_t)__cvta_generic_to_shared(base + 16384 + r * 128 + phys);
            const __half* gb = B + (size_t)(col0 + r) * 1536 + k0 + c * 8;
            asm volatile("cp.async.cg.shared.global [%0], [%1], 16;\n"
                         :: "r"(sb), "l"(gb) : "memory");
        }
        asm volatile("cp.async.commit_group;\n" ::: "memory");
    };

    load_stage(0, 0);
    load_stage(1, 1);

    const int lrow = lane & 15;
    const int lkh  = lane >> 4;

    for (int kt = 0; kt < HKT; kt++) {
        if (kt < HKT - 1) { asm volatile("cp.async.wait_group 1;\n" ::: "memory"); }
        else              { asm volatile("cp.async.wait_group 0;\n" ::: "memory"); }
        __syncthreads();
        if (kt + 2 < HKT) load_stage(kt + 2, (kt + 2) % HSTAGES);

        const char* Ab = sm + (kt % HSTAGES) * HSTAGE_BYTES;
        const char* Bb = Ab + 16384;

        #pragma unroll
        for (int kk = 0; kk < 4; kk++) {
            const int cbase = kk * 2 + lkh;
            uint32_t af[4][4], bf[4][2];
            #pragma unroll
            for (int im = 0; im < 4; im++) {
                int r = wm * 64 + im * 16 + lrow;
                uint32_t addr = (uint32_t)__cvta_generic_to_shared(
                    Ab + r * 128 + ((cbase ^ (r & 7)) << 4));
                ldsm4(af[im], addr);
            }
            #pragma unroll
            for (int i2 = 0; i2 < 2; i2++) {
                int r = wn * 32 + i2 * 16 + lrow;
                uint32_t addr = (uint32_t)__cvta_generic_to_shared(
                    Bb + r * 128 + ((cbase ^ (r & 7)) << 4));
                uint32_t t[4];
                ldsm4(t, addr);
                bf[i2 * 2][0] = t[0];     bf[i2 * 2][1] = t[2];
                bf[i2 * 2 + 1][0] = t[1]; bf[i2 * 2 + 1][1] = t[3];
            }
            #pragma unroll
            for (int im = 0; im < 4; im++)
                #pragma unroll
                for (int in = 0; in < 4; in++)
                    mma16816(acc[im][in], af[im], bf[in]);
        }
        __syncthreads();
    }

    // ---- epilogue ----
    const int tr = lane >> 2, tc = lane & 3;
    #pragma unroll
    for (int im = 0; im < 4; im++)
        #pragma unroll
        for (int in = 0; in < 4; in++)
            #pragma unroll
            for (int h = 0; h < 2; h++) {
                int row = row0 + wm * 64 + im * 16 + tr + h * 8;
                if (row >= M) continue;
                int col = col0 + wn * 32 + in * 8 + (tc << 1);
                float v0 = acc[im][in][h * 2 + 0] + bias[col];
                float v1 = acc[im][in][h * 2 + 1] + bias[col + 1];
                if (EPI == 1) {
                    int fi = (col & 127) >> 1;
                    float cc = g_ct[row * 64 + fi], ss = g_st[row * 64 + fi];
                    float a = v0, b = v1;
                    v0 = a * cc - b * ss;
                    v1 = b * cc + a * ss;
                    __half2 hh = __floats2half2_rn(v0, v1);
                    *reinterpret_cast<__half2*>((__half*)C + (size_t)row * DIM + col) = hh;
                } else {
                    *reinterpret_cast<float2*>((float*)C + (size_t)row * DIM + col) =
                        make_float2(v0, v1);
                }
            }
}

// ---------------- SIMT TF32 GEMM for the small kv projection ----------------
__device__ __forceinline__ uint32_t f2tf32(float f) {
    uint32_t r;
    asm("cvt.rna.tf32.f32 %0, %1;" : "=r"(r) : "f"(f));
    return r;
}
__device__ __forceinline__ void mma_tf32(float* d, const uint32_t* a, const uint32_t* b) {
    asm volatile(
        "mma.sync.aligned.m16n8k8.row.col.f32.tf32.tf32.f32 "
        "{%0,%1,%2,%3}, {%4,%5,%6,%7}, {%8,%9}, {%0,%1,%2,%3};\n"
        : "+f"(d[0]), "+f"(d[1]), "+f"(d[2]), "+f"(d[3])
        : "r"(a[0]), "r"(a[1]), "r"(a[2]), "r"(a[3]), "r"(b[0]), "r"(b[1]));
}
#define SMEM_KV (2 * 2 * 128 * 32 * 4)

__global__ __launch_bounds__(256)
void gemm_kv(const float* __restrict__ A, const float* __restrict__ B,
             const float* __restrict__ bias, float* __restrict__ C,
             int M, int N, int K) {
    extern __shared__ float smf[];
    float* As = smf;
    float* Bs = smf + 2 * 4096;
    const int tid = threadIdx.x, lane = tid & 31, warp = tid >> 5;
    const int wm = warp >> 2, wn = warp & 3;
    const int tr = lane >> 2, tc = lane & 3;
    const int row0 = blockIdx.y * 128, col0 = blockIdx.x * 128;
    const int KT = K >> 5;

    float acc[4][4][4];
    #pragma unroll
    for (int i = 0; i < 4; i++)
        #pragma unroll
        for (int j = 0; j < 4; j++)
            #pragma unroll
            for (int r = 0; r < 4; r++) acc[i][j][r] = 0.f;

    auto tile_load = [&](int kt, int buf) {
        int k0 = kt << 5;
        #pragma unroll
        for (int j = 0; j < 4; j++) {
            int L = tid + j * 256;
            int r = L >> 3, c4 = L & 7;
            int soff = buf * 4096 + r * 32 + ((c4 ^ (r & 7)) << 2);
            const float* ga = A + (size_t)(row0 + r) * K + k0 + (c4 << 2);
            uint32_t sa = (uint32_t)__cvta_generic_to_shared(As + soff);
            int sz = (row0 + r < M) ? 16 : 0;
            asm volatile("cp.async.cg.shared.global [%0], [%1], 16, %2;\n"
                         :: "r"(sa), "l"(ga), "r"(sz) : "memory");
            const float* gb = B + (size_t)(col0 + r) * K + k0 + (c4 << 2);
            uint32_t sb = (uint32_t)__cvta_generic_to_shared(Bs + soff);
            asm volatile("cp.async.cg.shared.global [%0], [%1], 16;\n"
                         :: "r"(sb), "l"(gb) : "memory");
        }
        asm volatile("cp.async.commit_group;\n" ::: "memory");
    };

    tile_load(0, 0);
    for (int kt = 0; kt < KT; ++kt) {
        asm volatile("cp.async.wait_group 0;\n" ::: "memory");
        __syncthreads();
        const int cur = kt & 1;
        if (kt + 1 < KT) tile_load(kt + 1, cur ^ 1);
        const float* Ab = As + cur * 4096;
        const float* Bb = Bs + cur * 4096;
        #pragma unroll
        for (int kk = 0; kk < 4; kk++) {
            const int kb = kk << 3;
            uint32_t af[4][4], bf[4][2];
            #pragma unroll
            for (int im = 0; im < 4; im++) {
                int rb = wm * 64 + im * 16;
                int r1 = rb + tr, r2 = rb + tr + 8;
                int k1 = kb + tc, k2 = kb + tc + 4;
                af[im][0] = f2tf32(Ab[r1 * 32 + (((k1 >> 2) ^ (r1 & 7)) << 2) + (k1 & 3)]);
                af[im][1] = f2tf32(Ab[r2 * 32 + (((k1 >> 2) ^ (r2 & 7)) << 2) + (k1 & 3)]);
                af[im][2] = f2tf32(Ab[r1 * 32 + (((k2 >> 2) ^ (r1 & 7)) << 2) + (k2 & 3)]);
                af[im][3] = f2tf32(Ab[r2 * 32 + (((k2 >> 2) ^ (r2 & 7)) << 2) + (k2 & 3)]);
            }
            #pragma unroll
            for (int in = 0; in < 4; in++) {
                int nb = wn * 32 + in * 8 + tr;
                int k1 = kb + tc, k2 = kb + tc + 4;
                bf[in][0] = f2tf32(Bb[nb * 32 + (((k1 >> 2) ^ (nb & 7)) << 2) + (k1 & 3)]);
                bf[in][1] = f2tf32(Bb[nb * 32 + (((k2 >> 2) ^ (nb & 7)) << 2) + (k2 & 3)]);
            }
            #pragma unroll
            for (int im = 0; im < 4; im++)
                #pragma unroll
                for (int in = 0; in < 4; in++)
                    mma_tf32(acc[im][in], af[im], bf[in]);
        }
        __syncthreads();
    }

    #pragma unroll
    for (int im = 0; im < 4; im++)
        #pragma unroll
        for (int in = 0; in < 4; in++)
            #pragma unroll
            for (int h = 0; h < 2; h++) {
                int row = row0 + wm * 64 + im * 16 + tr + h * 8;
                if (row >= M) continue;
                int col = col0 + wn * 32 + in * 8 + (tc << 1);
                float v0 = acc[im][in][h * 2 + 0] + bias[col];
                float v1 = acc[im][in][h * 2 + 1] + bias[col + 1];
                if (col < DIM) {   // k half: bucket-centre RoPE
                    int a = row & 31;
                    float pos = (a < 16) ? 2.0f : 22.0f;
                    int fi = (col & 127) >> 1;
                    float freq = expf(-(float)fi * (2.0f / 128.0f) * 9.210340371976184f);
                    float s, c;
                    sincosf(pos * freq, &s, &c);
                    float o0 = v0 * c - v1 * s;
                    float o1 = v1 * c + v0 * s;
                    v0 = o0; v1 = o1;
                }
                *reinterpret_cast<float2*>(C + (size_t)row * N + col) = make_float2(v0, v1);
            }
}

// ---------------- attention: per (frame, head), KV len 32 -------------------
// q fp16 in, fp16 out. K padded rows for conflict-free float4 lane reads,
// probs staged in smem (no shfl in AV loop).
#define SMEM_ATTN ((32 * 132 + 32 * 128 + 8 * 4 * 128 + 8 * 4 * 32) * 4)

__global__ __launch_bounds__(256)
void attn_kernel(const __half* __restrict__ q, const float* __restrict__ kv,
                 __half* __restrict__ out) {
    extern __shared__ float smA[];
    float* ks = smA;                 // [32][132] padded
    float* vs = ks + 32 * 132;       // [32][128]
    float* qb = vs + 32 * 128;       // [8 warps][4 rows][128]
    float* ps = qb + 8 * 4 * 128;    // [8 warps][4 rows][32]

    const int fh = blockIdx.x;
    const int f = fh / NHEAD, h = fh % NHEAD;
    const int tid = threadIdx.x, lane = tid & 31, warp = tid >> 5;

    const float* kvb = kv + (size_t)f * NA * KVN + h * HD;
    for (int idx = tid; idx < NA * HD; idx += 256) {
        int a = idx >> 7, d = idx & 127;
        ks[a * 132 + d] = kvb[(size_t)a * KVN + d];
        vs[idx] = kvb[(size_t)a * KVN + DIM + d];
    }
    __syncthreads();

    float* qw = qb + warp * 4 * 128;
    float* pw = ps + warp * 4 * 32;

    const int sbase = blockIdx.y * 128 + warp * 16;
    for (int g = 0; g < 4; ++g) {
        int s0 = sbase + g * 4;
        #pragma unroll
        for (int r = 0; r < 4; r++) {
            int s = min(s0 + r, S_SP - 1);
            uint2 raw = *reinterpret_cast<const uint2*>(
                q + (size_t)(f * S_SP + s) * DIM + h * HD + lane * 4);
            __half2 h0 = *reinterpret_cast<__half2*>(&raw.x);
            __half2 h1 = *reinterpret_cast<__half2*>(&raw.y);
            float2 f0 = __half22float2(h0);
            float2 f1 = __half22float2(h1);
            *reinterpret_cast<float4*>(qw + r * 128 + lane * 4) =
                make_float4(f0.x, f0.y, f1.x, f1.y);
        }
        __syncwarp();

        float sc[4] = {0.f, 0.f, 0.f, 0.f};
        #pragma unroll 8
        for (int d4 = 0; d4 < 32; d4++) {
            float4 k4 = *reinterpret_cast<const float4*>(ks + lane * 132 + d4 * 4);
            #pragma unroll
            for (int r = 0; r < 4; r++) {
                float4 q4 = *reinterpret_cast<const float4*>(qw + r * 128 + d4 * 4);
                sc[r] = fmaf(q4.x, k4.x, sc[r]);
                sc[r] = fmaf(q4.y, k4.y, sc[r]);
                sc[r] = fmaf(q4.z, k4.z, sc[r]);
                sc[r] = fmaf(q4.w, k4.w, sc[r]);
            }
        }

        #pragma unroll
        for (int r = 0; r < 4; r++) {
            float x = sc[r] * 0.08838834764831845f;
            float mx = x;
            #pragma unroll
            for (int o = 16; o > 0; o >>= 1) mx = fmaxf(mx, __shfl_xor_sync(0xffffffffu, mx, o));
            float e = expf(x - mx);
            float sum = e;
            #pragma unroll
            for (int o = 16; o > 0; o >>= 1) sum += __shfl_xor_sync(0xffffffffu, sum, o);
            pw[r * 32 + lane] = e / sum;
        }
        __syncwarp();

        float4 ac[4];
        #pragma unroll
        for (int r = 0; r < 4; r++) ac[r] = make_float4(0.f, 0.f, 0.f, 0.f);
        #pragma unroll
        for (int a4 = 0; a4 < 8; a4++) {
            float4 pv[4];
            #pragma unroll
            for (int r = 0; r < 4; r++)
                pv[r] = *reinterpret_cast<const float4*>(pw + r * 32 + a4 * 4);
            #pragma unroll
            for (int j = 0; j < 4; j++) {
                float4 va = *reinterpret_cast<const float4*>(vs + (a4 * 4 + j) * 128 + lane * 4);
                #pragma unroll
                for (int r = 0; r < 4; r++) {
                    float pa = (j == 0) ? pv[r].x : (j == 1) ? pv[r].y : (j == 2) ? pv[r].z : pv[r].w;
                    ac[r].x = fmaf(pa, va.x, ac[r].x);
                    ac[r].y = fmaf(pa, va.y, ac[r].y);
                    ac[r].z = fmaf(pa, va.z, ac[r].z);
                    ac[r].w = fmaf(pa, va.w, ac[r].w);
                }
            }
        }
        #pragma unroll
        for (int r = 0; r < 4; r++) {
            int s = s0 + r;
            if (s < S_SP) {
                __half2 h0 = __floats2half2_rn(ac[r].x, ac[r].y);
                __half2 h1 = __floats2half2_rn(ac[r].z, ac[r].w);
                uint2 o;
                o.x = *reinterpret_cast<uint32_t*>(&h0);
                o.y = *reinterpret_cast<uint32_t*>(&h1);
                *reinterpret_cast<uint2*>(
                    out + (size_t)(f * S_SP + s) * DIM + h * HD + lane * 4) = o;
            }
        }
        __syncwarp();
    }
}

// ---------------- launch ----------------
extern "C" void kernel_launch(void* const* d_in, const int* in_sizes, int n_in,
                              void* d_out, int out_size) {
    const float* x      = (const float*)d_in[0];
    const float* enc    = (const float*)d_in[1];
    const float* m      = (const float*)d_in[2];
    const float* q_w    = (const float*)d_in[3];
    const float* q_b    = (const float*)d_in[4];
    const float* kv_w   = (const float*)d_in[5];
    const float* kv_b   = (const float*)d_in[6];
    const float* proj_w = (const float*)d_in[7];
    const float* proj_b = (const float*)d_in[8];
    float* out = (float*)d_out;

    float* kvbuf;
    __half *xh, *qwh, *pwh, *qh, *attnh;
    cudaGetSymbolAddress((void**)&kvbuf, g_kv);
    cudaGetSymbolAddress((void**)&xh, g_xh);
    cudaGetSymbolAddress((void**)&qwh, g_qwh);
    cudaGetSymbolAddress((void**)&pwh, g_pwh);
    cudaGetSymbolAddress((void**)&qh, g_qh);
    cudaGetSymbolAddress((void**)&attnh, g_attnh);

    cudaFuncSetAttribute(gemm_h<0, float>, cudaFuncAttributeMaxDynamicSharedMemorySize, SMEM_H);
    cudaFuncSetAttribute(gemm_h<1, __half>, cudaFuncAttributeMaxDynamicSharedMemorySize, SMEM_H);
    cudaFuncSetAttribute(gemm_kv, cudaFuncAttributeMaxDynamicSharedMemorySize, SMEM_KV);
    cudaFuncSetAttribute(attn_kernel, cudaFuncAttributeMaxDynamicSharedMemorySize, SMEM_ATTN);

    minmax_kernel<<<1, 1024>>>(m, NTS);
    table_kernel<<<(NTS * 64 + 255) / 256, 256>>>(m, NTS);

    long nx4 = (long)NTS * DIM / 4, nw4 = (long)DIM * DIM / 4;
    f2h_kernel<<<(unsigned)((nx4 + 255) / 256), 256>>>(x, xh, nx4);
    f2h_kernel<<<(unsigned)((nw4 + 255) / 256), 256>>>(q_w, qwh, nw4);
    f2h_kernel<<<(unsigned)((nw4 + 255) / 256), 256>>>(proj_w, pwh, nw4);

    // q = x @ q_w^T + q_b, fused token RoPE, fp16 out
    gemm_h<1, __half><<<dim3(DIM / 128, (NTS + 127) / 128), 256, SMEM_H>>>(
        xh, qwh, q_b, qh, NTS);
    // kv = enc @ kv_w^T + kv_b, bucket RoPE on k half
    gemm_kv<<<dim3(KVN / 128, (NT * NA + 127) / 128), 256, SMEM_KV>>>(
        enc, kv_w, kv_b, kvbuf, NT * NA, KVN, ENC);
    // cross attention (fp16 in, fp16 out)
    attn_kernel<<<dim3(NT * NHEAD, 13), 256, SMEM_ATTN>>>(qh, kvbuf, attnh);
    // out = attn @ proj_w^T + proj_b, fp32 out
    gemm_h<0, float><<<dim3(DIM / 128, (NTS + 127) / 128), 256, SMEM_H>>>(
        attnh, pwh, proj_b, out, NTS);
}

// round 12
// speedup vs baseline: 1.5841x; 1.1379x over previous
#include <cuda_runtime.h>
#include <cuda_fp16.h>
#include <cstdint>
#include <math.h>

// ---------------- problem constants (fixed by setup_inputs) ----------------
#define NT    21
#define S_SP  1560
#define NTS   32760
#define DIM   1536
#define ENC   768
#define NA    32
#define NHEAD 12
#define HD    128
#define KVN   3072

// ---------------- scratch (static device globals) ----------------
__device__ float  g_mm[4];
__device__ float  g_ct[NTS * 64];
__device__ float  g_st[NTS * 64];
__device__ float  g_kv[(size_t)NT * NA * KVN];   // kv after GEMM (fp32)
__device__ __half g_xh[(size_t)NTS * DIM];       // x in fp16
__device__ __half g_qwh[(size_t)DIM * DIM];      // q_w in fp16
__device__ __half g_pwh[(size_t)DIM * DIM];      // proj_w in fp16
__device__ __half g_qh[(size_t)NTS * DIM];       // q after GEMM+RoPE (fp16)
__device__ __half g_attnh[(size_t)NTS * DIM];    // attention output (fp16)

// ---------------- fp32 -> fp16 conversion ----------------
__global__ void f2h_kernel(const float* __restrict__ in, __half* __restrict__ out, long n4) {
    long i = (long)blockIdx.x * blockDim.x + threadIdx.x;
    if (i >= n4) return;
    float4 v = reinterpret_cast<const float4*>(in)[i];
    __half2 h0 = __floats2half2_rn(v.x, v.y);
    __half2 h1 = __floats2half2_rn(v.z, v.w);
    uint2 o;
    o.x = *reinterpret_cast<uint32_t*>(&h0);
    o.y = *reinterpret_cast<uint32_t*>(&h1);
    reinterpret_cast<uint2*>(out)[i] = o;
}

// ---------------- min/max of the two attn-map rows ----------------
__global__ void minmax_kernel(const float* __restrict__ m, int n) {
    const int tid = threadIdx.x, lane = tid & 31, warp = tid >> 5;
    float mn0 = 1e30f, mx0 = -1e30f, mn1 = 1e30f, mx1 = -1e30f;
    for (int i = tid; i < n; i += blockDim.x) {
        float a = m[i], b = m[n + i];
        mn0 = fminf(mn0, a); mx0 = fmaxf(mx0, a);
        mn1 = fminf(mn1, b); mx1 = fmaxf(mx1, b);
    }
    #pragma unroll
    for (int o = 16; o > 0; o >>= 1) {
        mn0 = fminf(mn0, __shfl_xor_sync(0xffffffffu, mn0, o));
        mx0 = fmaxf(mx0, __shfl_xor_sync(0xffffffffu, mx0, o));
        mn1 = fminf(mn1, __shfl_xor_sync(0xffffffffu, mn1, o));
        mx1 = fmaxf(mx1, __shfl_xor_sync(0xffffffffu, mx1, o));
    }
    __shared__ float s0[32], s1[32], s2[32], s3[32];
    if (lane == 0) { s0[warp] = mn0; s1[warp] = mx0; s2[warp] = mn1; s3[warp] = mx1; }
    __syncthreads();
    if (warp == 0) {
        int nw = blockDim.x >> 5;
        mn0 = (lane < nw) ? s0[lane] : 1e30f;
        mx0 = (lane < nw) ? s1[lane] : -1e30f;
        mn1 = (lane < nw) ? s2[lane] : 1e30f;
        mx1 = (lane < nw) ? s3[lane] : -1e30f;
        #pragma unroll
        for (int o = 16; o > 0; o >>= 1) {
            mn0 = fminf(mn0, __shfl_xor_sync(0xffffffffu, mn0, o));
            mx0 = fmaxf(mx0, __shfl_xor_sync(0xffffffffu, mx0, o));
            mn1 = fminf(mn1, __shfl_xor_sync(0xffffffffu, mn1, o));
            mx1 = fmaxf(mx1, __shfl_xor_sync(0xffffffffu, mx1, o));
        }
        if (lane == 0) { g_mm[0] = mn0; g_mm[1] = mx0; g_mm[2] = mn1; g_mm[3] = mx1; }
    }
}

// ---------------- per-(token,freq) cos/sin table ----------------
__global__ void table_kernel(const float* __restrict__ m, int n) {
    int idx = blockIdx.x * blockDim.x + threadIdx.x;
    if (idx >= n * 64) return;
    int t = idx >> 6, i = idx & 63;
    float mn0 = g_mm[0], mx0 = g_mm[1], mn1 = g_mm[2], mx1 = g_mm[3];
    float m0 = m[t], m1 = m[n + t];
    float h1 = (m0 - mn0) / (mx0 - mn0 + 1e-8f) * 4.0f;
    float h2 = (m1 - mn1) / (mx1 - mn1 + 1e-8f) * 4.0f + 20.0f;
    float pos = (m0 >= m1) ? h1 : h2;
    float freq = expf(-(float)i * (2.0f / 128.0f) * 9.210340371976184f);
    float s, c;
    sincosf(pos * freq, &s, &c);
    g_ct[idx] = c;
    g_st[idx] = s;
}

// ---------------- shared MMA helpers ----------------
__device__ __forceinline__ void mma16816(float* d, const uint32_t* a, const uint32_t* b) {
    asm volatile(
        "mma.sync.aligned.m16n8k16.row.col.f32.f16.f16.f32 "
        "{%0,%1,%2,%3}, {%4,%5,%6,%7}, {%8,%9}, {%0,%1,%2,%3};\n"
        : "+f"(d[0]), "+f"(d[1]), "+f"(d[2]), "+f"(d[3])
        : "r"(a[0]), "r"(a[1]), "r"(a[2]), "r"(a[3]), "r"(b[0]), "r"(b[1]));
}
__device__ __forceinline__ void ldsm4(uint32_t* r, uint32_t addr) {
    asm volatile("ldmatrix.sync.aligned.m8n8.x4.shared.b16 {%0,%1,%2,%3}, [%4];"
                 : "=r"(r[0]), "=r"(r[1]), "=r"(r[2]), "=r"(r[3]) : "r"(addr));
}
__device__ __forceinline__ void ldsm4t(uint32_t* r, uint32_t addr) {
    asm volatile("ldmatrix.sync.aligned.m8n8.x4.trans.shared.b16 {%0,%1,%2,%3}, [%4];"
                 : "=r"(r[0]), "=r"(r[1]), "=r"(r[2]), "=r"(r[3]) : "r"(addr));
}
__device__ __forceinline__ uint32_t pack_h2(float a, float b) {
    __half2 h = __floats2half2_rn(a, b);
    return *reinterpret_cast<uint32_t*>(&h);
}

// ---------------- fp16 GEMM: C[M,1536] = A[M,1536] @ B[1536,1536]^T + bias --
// (R6/R8 proven config) ldmatrix + mma.m16n8k16, 128x128 tile, BK=64, 3 stages.
#define HBK 64
#define HSTAGE_BYTES (128 * HBK * 2 * 2)
#define HSTAGES 3
#define SMEM_H (HSTAGES * HSTAGE_BYTES)       // 98304 -> 2 CTAs/SM
#define HKT (1536 / HBK)

template <int EPI, typename OT>
__global__ __launch_bounds__(256)
void gemm_h(const __half* __restrict__ A, const __half* __restrict__ B,
            const float* __restrict__ bias, OT* __restrict__ C, int M) {
    extern __shared__ char sm[];
    const int tid = threadIdx.x, lane = tid & 31, warp = tid >> 5;
    const int wm = warp >> 2, wn = warp & 3;
    const int row0 = blockIdx.y * 128, col0 = blockIdx.x * 128;

    float acc[4][4][4];
    #pragma unroll
    for (int i = 0; i < 4; i++)
        #pragma unroll
        for (int j = 0; j < 4; j++)
            #pragma unroll
            for (int r = 0; r < 4; r++) acc[i][j][r] = 0.f;

    auto load_stage = [&](int kt, int s) {
        const int k0 = kt * HBK;
        char* base = sm + s * HSTAGE_BYTES;
        #pragma unroll
        for (int j = 0; j < 4; j++) {
            int id = tid + j * 256;
            int r = id >> 3, c = id & 7;
            int phys = (c ^ (r & 7)) << 4;
            uint32_t sa = (uint32_t)__cvta_generic_to_shared(base + r * 128 + phys);
            const __half* ga = A + (size_t)(row0 + r) * 1536 + k0 + c * 8;
            int sz = (row0 + r < M) ? 16 : 0;
            asm volatile("cp.async.cg.shared.global [%0], [%1], 16, %2;\n"
                         :: "r"(sa), "l"(ga), "r"(sz) : "memory");
            uint32_t sb = (uint32_t)__cvta_generic_to_shared(base + 16384 + r * 128 + phys);
            const __half* gb = B + (size_t)(col0 + r) * 1536 + k0 + c * 8;
            asm volatile("cp.async.cg.shared.global [%0], [%1], 16;\n"
                         :: "r"(sb), "l"(gb) : "memory");
        }
        asm volatile("cp.async.commit_group;\n" ::: "memory");
    };

    load_stage(0, 0);
    load_stage(1, 1);

    const int lrow = lane & 15;
    const int lkh  = lane >> 4;

    for (int kt = 0; kt < HKT; kt++) {
        if (kt < HKT - 1) { asm volatile("cp.async.wait_group 1;\n" ::: "memory"); }
        else              { asm volatile("cp.async.wait_group 0;\n" ::: "memory"); }
        __syncthreads();
        if (kt + 2 < HKT) load_stage(kt + 2, (kt + 2) % HSTAGES);

        const char* Ab = sm + (kt % HSTAGES) * HSTAGE_BYTES;
        const char* Bb = Ab + 16384;

        #pragma unroll
        for (int kk = 0; kk < 4; kk++) {
            const int cbase = kk * 2 + lkh;
            uint32_t af[4][4], bf[4][2];
            #pragma unroll
            for (int im = 0; im < 4; im++) {
                int r = wm * 64 + im * 16 + lrow;
                uint32_t addr = (uint32_t)__cvta_generic_to_shared(
                    Ab + r * 128 + ((cbase ^ (r & 7)) << 4));
                ldsm4(af[im], addr);
            }
            #pragma unroll
            for (int i2 = 0; i2 < 2; i2++) {
                int r = wn * 32 + i2 * 16 + lrow;
                uint32_t addr = (uint32_t)__cvta_generic_to_shared(
                    Bb + r * 128 + ((cbase ^ (r & 7)) << 4));
                uint32_t t[4];
                ldsm4(t, addr);
                bf[i2 * 2][0] = t[0];     bf[i2 * 2][1] = t[2];
                bf[i2 * 2 + 1][0] = t[1]; bf[i2 * 2 + 1][1] = t[3];
            }
            #pragma unroll
            for (int im = 0; im < 4; im++)
                #pragma unroll
                for (int in = 0; in < 4; in++)
                    mma16816(acc[im][in], af[im], bf[in]);
        }
        __syncthreads();
    }

    const int tr = lane >> 2, tc = lane & 3;
    #pragma unroll
    for (int im = 0; im < 4; im++)
        #pragma unroll
        for (int in = 0; in < 4; in++)
            #pragma unroll
            for (int h = 0; h < 2; h++) {
                int row = row0 + wm * 64 + im * 16 + tr + h * 8;
                if (row >= M) continue;
                int col = col0 + wn * 32 + in * 8 + (tc << 1);
                float v0 = acc[im][in][h * 2 + 0] + bias[col];
                float v1 = acc[im][in][h * 2 + 1] + bias[col + 1];
                if (EPI == 1) {
                    int fi = (col & 127) >> 1;
                    float cc = g_ct[row * 64 + fi], ss = g_st[row * 64 + fi];
                    float a = v0, b = v1;
                    v0 = a * cc - b * ss;
                    v1 = b * cc + a * ss;
                    __half2 hh = __floats2half2_rn(v0, v1);
                    *reinterpret_cast<__half2*>((__half*)C + (size_t)row * DIM + col) = hh;
                } else {
                    *reinterpret_cast<float2*>((float*)C + (size_t)row * DIM + col) =
                        make_float2(v0, v1);
                }
            }
}

// ---------------- SIMT TF32 GEMM for the small kv projection ----------------
__device__ __forceinline__ uint32_t f2tf32(float f) {
    uint32_t r;
    asm("cvt.rna.tf32.f32 %0, %1;" : "=r"(r) : "f"(f));
    return r;
}
__device__ __forceinline__ void mma_tf32(float* d, const uint32_t* a, const uint32_t* b) {
    asm volatile(
        "mma.sync.aligned.m16n8k8.row.col.f32.tf32.tf32.f32 "
        "{%0,%1,%2,%3}, {%4,%5,%6,%7}, {%8,%9}, {%0,%1,%2,%3};\n"
        : "+f"(d[0]), "+f"(d[1]), "+f"(d[2]), "+f"(d[3])
        : "r"(a[0]), "r"(a[1]), "r"(a[2]), "r"(a[3]), "r"(b[0]), "r"(b[1]));
}
#define SMEM_KV (2 * 2 * 128 * 32 * 4)

__global__ __launch_bounds__(256)
void gemm_kv(const float* __restrict__ A, const float* __restrict__ B,
             const float* __restrict__ bias, float* __restrict__ C,
             int M, int N, int K) {
    extern __shared__ float smf[];
    float* As = smf;
    float* Bs = smf + 2 * 4096;
    const int tid = threadIdx.x, lane = tid & 31, warp = tid >> 5;
    const int wm = warp >> 2, wn = warp & 3;
    const int tr = lane >> 2, tc = lane & 3;
    const int row0 = blockIdx.y * 128, col0 = blockIdx.x * 128;
    const int KT = K >> 5;

    float acc[4][4][4];
    #pragma unroll
    for (int i = 0; i < 4; i++)
        #pragma unroll
        for (int j = 0; j < 4; j++)
            #pragma unroll
            for (int r = 0; r < 4; r++) acc[i][j][r] = 0.f;

    auto tile_load = [&](int kt, int buf) {
        int k0 = kt << 5;
        #pragma unroll
        for (int j = 0; j < 4; j++) {
            int L = tid + j * 256;
            int r = L >> 3, c4 = L & 7;
            int soff = buf * 4096 + r * 32 + ((c4 ^ (r & 7)) << 2);
            const float* ga = A + (size_t)(row0 + r) * K + k0 + (c4 << 2);
            uint32_t sa = (uint32_t)__cvta_generic_to_shared(As + soff);
            int sz = (row0 + r < M) ? 16 : 0;
            asm volatile("cp.async.cg.shared.global [%0], [%1], 16, %2;\n"
                         :: "r"(sa), "l"(ga), "r"(sz) : "memory");
            const float* gb = B + (size_t)(col0 + r) * K + k0 + (c4 << 2);
            uint32_t sb = (uint32_t)__cvta_generic_to_shared(Bs + soff);
            asm volatile("cp.async.cg.shared.global [%0], [%1], 16;\n"
                         :: "r"(sb), "l"(gb) : "memory");
        }
        asm volatile("cp.async.commit_group;\n" ::: "memory");
    };

    tile_load(0, 0);
    for (int kt = 0; kt < KT; ++kt) {
        asm volatile("cp.async.wait_group 0;\n" ::: "memory");
        __syncthreads();
        const int cur = kt & 1;
        if (kt + 1 < KT) tile_load(kt + 1, cur ^ 1);
        const float* Ab = As + cur * 4096;
        const float* Bb = Bs + cur * 4096;
        #pragma unroll
        for (int kk = 0; kk < 4; kk++) {
            const int kb = kk << 3;
            uint32_t af[4][4], bf[4][2];
            #pragma unroll
            for (int im = 0; im < 4; im++) {
                int rb = wm * 64 + im * 16;
                int r1 = rb + tr, r2 = rb + tr + 8;
                int k1 = kb + tc, k2 = kb + tc + 4;
                af[im][0] = f2tf32(Ab[r1 * 32 + (((k1 >> 2) ^ (r1 & 7)) << 2) + (k1 & 3)]);
                af[im][1] = f2tf32(Ab[r2 * 32 + (((k1 >> 2) ^ (r2 & 7)) << 2) + (k1 & 3)]);
                af[im][2] = f2tf32(Ab[r1 * 32 + (((k2 >> 2) ^ (r1 & 7)) << 2) + (k2 & 3)]);
                af[im][3] = f2tf32(Ab[r2 * 32 + (((k2 >> 2) ^ (r2 & 7)) << 2) + (k2 & 3)]);
            }
            #pragma unroll
            for (int in = 0; in < 4; in++) {
                int nb = wn * 32 + in * 8 + tr;
                int k1 = kb + tc, k2 = kb + tc + 4;
                bf[in][0] = f2tf32(Bb[nb * 32 + (((k1 >> 2) ^ (nb & 7)) << 2) + (k1 & 3)]);
                bf[in][1] = f2tf32(Bb[nb * 32 + (((k2 >> 2) ^ (nb & 7)) << 2) + (k2 & 3)]);
            }
            #pragma unroll
            for (int im = 0; im < 4; im++)
                #pragma unroll
                for (int in = 0; in < 4; in++)
                    mma_tf32(acc[im][in], af[im], bf[in]);
        }
        __syncthreads();
    }

    #pragma unroll
    for (int im = 0; im < 4; im++)
        #pragma unroll
        for (int in = 0; in < 4; in++)
            #pragma unroll
            for (int h = 0; h < 2; h++) {
                int row = row0 + wm * 64 + im * 16 + tr + h * 8;
                if (row >= M) continue;
                int col = col0 + wn * 32 + in * 8 + (tc << 1);
                float v0 = acc[im][in][h * 2 + 0] + bias[col];
                float v1 = acc[im][in][h * 2 + 1] + bias[col + 1];
                if (col < DIM) {
                    int a = row & 31;
                    float pos = (a < 16) ? 2.0f : 22.0f;
                    int fi = (col & 127) >> 1;
                    float freq = expf(-(float)fi * (2.0f / 128.0f) * 9.210340371976184f);
                    float s, c;
                    sincosf(pos * freq, &s, &c);
                    float o0 = v0 * c - v1 * s;
                    float o1 = v1 * c + v0 * s;
                    v0 = o0; v1 = o1;
                }
                *reinterpret_cast<float2*>(C + (size_t)row * N + col) = make_float2(v0, v1);
            }
}

// ---------------- tensor-core attention: per (frame, head), KV len 32 -------
// Q (fp16) + K,V (fp32->fp16) in smem; scores and AV via mma.m16n8k16;
// softmax done in C-fragment registers. Pitch 136 halves -> conflict-free ldsm.
#define APITCH 136
#define SMEM_ATTN ((128 + 32 + 32) * APITCH * 2)   // 52224 bytes

__global__ __launch_bounds__(256, 2)
void attn_kernel(const __half* __restrict__ q, const float* __restrict__ kv,
                 __half* __restrict__ out) {
    extern __shared__ __half smh[];
    __half* Qs = smh;                    // [128][APITCH]
    __half* Ks = Qs + 128 * APITCH;      // [32][APITCH]
    __half* Vs = Ks + 32 * APITCH;       // [32][APITCH]

    const int fh = blockIdx.x;
    const int f = fh / NHEAD, h = fh % NHEAD;
    const int tid = threadIdx.x, lane = tid & 31, warp = tid >> 5;
    const int t0 = blockIdx.y * 128;

    // Q: 128 rows x 16 chunks of 8 halves
    for (int idx = tid; idx < 128 * 16; idx += 256) {
        int r = idx >> 4, c = idx & 15;
        int s = min(t0 + r, S_SP - 1);
        uint4 v = *reinterpret_cast<const uint4*>(
            q + (size_t)(f * S_SP + s) * DIM + h * HD + c * 8);
        *reinterpret_cast<uint4*>(Qs + r * APITCH + c * 8) = v;
    }
    // K, V: fp32 -> fp16
    const float* kvb = kv + (size_t)f * NA * KVN + h * HD;
    for (int idx = tid; idx < 32 * 32; idx += 256) {
        int a = idx >> 5, d4 = idx & 31;
        float4 kx = *reinterpret_cast<const float4*>(kvb + (size_t)a * KVN + d4 * 4);
        float4 vx = *reinterpret_cast<const float4*>(kvb + (size_t)a * KVN + DIM + d4 * 4);
        uint2 kp, vp;
        kp.x = pack_h2(kx.x, kx.y); kp.y = pack_h2(kx.z, kx.w);
        vp.x = pack_h2(vx.x, vx.y); vp.y = pack_h2(vx.z, vx.w);
        *reinterpret_cast<uint2*>(Ks + a * APITCH + d4 * 4) = kp;
        *reinterpret_cast<uint2*>(Vs + a * APITCH + d4 * 4) = vp;
    }
    __syncthreads();

    const int lrow = lane & 15;
    const int lkh  = lane >> 4;
    const int tr = lane >> 2, tc = lane & 3;

    // ---- scores: S[16 tokens x 32 kv] per warp ----
    float sc[4][4];
    #pragma unroll
    for (int j = 0; j < 4; j++)
        #pragma unroll
        for (int r = 0; r < 4; r++) sc[j][r] = 0.f;

    #pragma unroll
    for (int ks = 0; ks < 8; ks++) {
        uint32_t af[4], b0[4], b1[4];
        ldsm4(af, (uint32_t)__cvta_generic_to_shared(
            Qs + (warp * 16 + lrow) * APITCH + ks * 16 + lkh * 8));
        ldsm4(b0, (uint32_t)__cvta_generic_to_shared(
            Ks + lrow * APITCH + ks * 16 + lkh * 8));
        ldsm4(b1, (uint32_t)__cvta_generic_to_shared(
            Ks + (16 + lrow) * APITCH + ks * 16 + lkh * 8));
        uint32_t bf[2];
        bf[0] = b0[0]; bf[1] = b0[2]; mma16816(sc[0], af, bf);
        bf[0] = b0[1]; bf[1] = b0[3]; mma16816(sc[1], af, bf);
        bf[0] = b1[0]; bf[1] = b1[2]; mma16816(sc[2], af, bf);
        bf[0] = b1[1]; bf[1] = b1[3]; mma16816(sc[3], af, bf);
    }

    // ---- softmax in fragments (rows tr and tr+8; 8 cols per thread/row) ----
    const float scale = 0.08838834764831845f;   // 1/sqrt(128)
    float mx0 = -1e30f, mx1 = -1e30f;
    #pragma unroll
    for (int j = 0; j < 4; j++) {
        sc[j][0] *= scale; sc[j][1] *= scale; sc[j][2] *= scale; sc[j][3] *= scale;
        mx0 = fmaxf(mx0, fmaxf(sc[j][0], sc[j][1]));
        mx1 = fmaxf(mx1, fmaxf(sc[j][2], sc[j][3]));
    }
    #pragma unroll
    for (int o = 1; o <= 2; o <<= 1) {
        mx0 = fmaxf(mx0, __shfl_xor_sync(0xffffffffu, mx0, o));
        mx1 = fmaxf(mx1, __shfl_xor_sync(0xffffffffu, mx1, o));
    }
    float sum0 = 0.f, sum1 = 0.f;
    #pragma unroll
    for (int j = 0; j < 4; j++) {
        sc[j][0] = expf(sc[j][0] - mx0); sum0 += sc[j][0];
        sc[j][1] = expf(sc[j][1] - mx0); sum0 += sc[j][1];
        sc[j][2] = expf(sc[j][2] - mx1); sum1 += sc[j][2];
        sc[j][3] = expf(sc[j][3] - mx1); sum1 += sc[j][3];
    }
    #pragma unroll
    for (int o = 1; o <= 2; o <<= 1) {
        sum0 += __shfl_xor_sync(0xffffffffu, sum0, o);
        sum1 += __shfl_xor_sync(0xffffffffu, sum1, o);
    }
    float inv0 = 1.0f / sum0, inv1 = 1.0f / sum1;
    #pragma unroll
    for (int j = 0; j < 4; j++) {
        sc[j][0] *= inv0; sc[j][1] *= inv0;
        sc[j][2] *= inv1; sc[j][3] *= inv1;
    }

    // pack P into A-fragments: k-step0 = kv tiles 0,1; k-step1 = tiles 2,3
    uint32_t pa[2][4];
    pa[0][0] = pack_h2(sc[0][0], sc[0][1]);
    pa[0][1] = pack_h2(sc[0][2], sc[0][3]);
    pa[0][2] = pack_h2(sc[1][0], sc[1][1]);
    pa[0][3] = pack_h2(sc[1][2], sc[1][3]);
    pa[1][0] = pack_h2(sc[2][0], sc[2][1]);
    pa[1][1] = pack_h2(sc[2][2], sc[2][3]);
    pa[1][2] = pack_h2(sc[3][0], sc[3][1]);
    pa[1][3] = pack_h2(sc[3][2], sc[3][3]);

    // ---- AV: O[16 x 128] per warp ----
    float av[16][4];
    #pragma unroll
    for (int n = 0; n < 16; n++)
        #pragma unroll
        for (int r = 0; r < 4; r++) av[n][r] = 0.f;

    const int g = lane >> 3, lr = lane & 7;
    #pragma unroll
    for (int nc = 0; nc < 8; nc++) {
        #pragma unroll
        for (int ks = 0; ks < 2; ks++) {
            uint32_t t[4];
            // lanes: g&1 -> kv row +8 half, g>>1 -> hd col +8 half
            int row = ks * 16 + (g & 1) * 8 + lr;
            int col = nc * 16 + (g >> 1) * 8;
            ldsm4t(t, (uint32_t)__cvta_generic_to_shared(Vs + row * APITCH + col));
            uint32_t bf[2];
            bf[0] = t[0]; bf[1] = t[1]; mma16816(av[nc * 2],     pa[ks], bf);
            bf[0] = t[2]; bf[1] = t[3]; mma16816(av[nc * 2 + 1], pa[ks], bf);
        }
    }

    // ---- store ----
    const int rowtok = t0 + warp * 16;
    #pragma unroll
    for (int n = 0; n < 16; n++) {
        int col = h * HD + n * 8 + tc * 2;
        int s1 = rowtok + tr;
        if (s1 < S_SP)
            *reinterpret_cast<__half2*>(out + (size_t)(f * S_SP + s1) * DIM + col) =
                __floats2half2_rn(av[n][0], av[n][1]);
        int s2 = rowtok + tr + 8;
        if (s2 < S_SP)
            *reinterpret_cast<__half2*>(out + (size_t)(f * S_SP + s2) * DIM + col) =
                __floats2half2_rn(av[n][2], av[n][3]);
    }
}

// ---------------- launch ----------------
extern "C" void kernel_launch(void* const* d_in, const int* in_sizes, int n_in,
                              void* d_out, int out_size) {
    const float* x      = (const float*)d_in[0];
    const float* enc    = (const float*)d_in[1];
    const float* m      = (const float*)d_in[2];
    const float* q_w    = (const float*)d_in[3];
    const float* q_b    = (const float*)d_in[4];
    const float* kv_w   = (const float*)d_in[5];
    const float* kv_b   = (const float*)d_in[6];
    const float* proj_w = (const float*)d_in[7];
    const float* proj_b = (const float*)d_in[8];
    float* out = (float*)d_out;

    float* kvbuf;
    __half *xh, *qwh, *pwh, *qh, *attnh;
    cudaGetSymbolAddress((void**)&kvbuf, g_kv);
    cudaGetSymbolAddress((void**)&xh, g_xh);
    cudaGetSymbolAddress((void**)&qwh, g_qwh);
    cudaGetSymbolAddress((void**)&pwh, g_pwh);
    cudaGetSymbolAddress((void**)&qh, g_qh);
    cudaGetSymbolAddress((void**)&attnh, g_attnh);

    cudaFuncSetAttribute(gemm_h<0, float>, cudaFuncAttributeMaxDynamicSharedMemorySize, SMEM_H);
    cudaFuncSetAttribute(gemm_h<1, __half>, cudaFuncAttributeMaxDynamicSharedMemorySize, SMEM_H);
    cudaFuncSetAttribute(gemm_kv, cudaFuncAttributeMaxDynamicSharedMemorySize, SMEM_KV);
    cudaFuncSetAttribute(attn_kernel, cudaFuncAttributeMaxDynamicSharedMemorySize, SMEM_ATTN);

    minmax_kernel<<<1, 1024>>>(m, NTS);
    table_kernel<<<(NTS * 64 + 255) / 256, 256>>>(m, NTS);

    long nx4 = (long)NTS * DIM / 4, nw4 = (long)DIM * DIM / 4;
    f2h_kernel<<<(unsigned)((nx4 + 255) / 256), 256>>>(x, xh, nx4);
    f2h_kernel<<<(unsigned)((nw4 + 255) / 256), 256>>>(q_w, qwh, nw4);
    f2h_kernel<<<(unsigned)((nw4 + 255) / 256), 256>>>(proj_w, pwh, nw4);

    // q = x @ q_w^T + q_b, fused token RoPE, fp16 out
    gemm_h<1, __half><<<dim3(DIM / 128, (NTS + 127) / 128), 256, SMEM_H>>>(
        xh, qwh, q_b, qh, NTS);
    // kv = enc @ kv_w^T + kv_b, bucket RoPE on k half
    gemm_kv<<<dim3(KVN / 128, (NT * NA + 127) / 128), 256, SMEM_KV>>>(
        enc, kv_w, kv_b, kvbuf, NT * NA, KVN, ENC);
    // cross attention (tensor cores, fp16)
    attn_kernel<<<dim3(NT * NHEAD, 13), 256, SMEM_ATTN>>>(qh, kvbuf, attnh);
    // out = attn @ proj_w^T + proj_b, fp32 out
    gemm_h<0, float><<<dim3(DIM / 128, (NTS + 127) / 128), 256, SMEM_H>>>(
        attnh, pwh, proj_b, out, NTS);
}